// round 11
// baseline (speedup 1.0000x reference)
#include <cuda_runtime.h>
#include <cuda_bf16.h>
#include <cstdint>

#define N_NODES   100000
#define N_EDGES   1600000
#define N_FEAT    512
#define HIDDEN    128
#define N_CLASSES 64

#define NB_SCAN   ((N_NODES + 1023) / 1024)   // 98

// ---------------- scratch (static device globals; no allocation) -------------
__device__ float g_h1[N_NODES * HIDDEN];      // x @ W1
__device__ float g_h [N_NODES * HIDDEN];      // relu(prop1 + b1)
__device__ float g_h2[N_NODES * N_CLASSES];   // h @ W2
__device__ int   g_counts[N_NODES];
__device__ int   g_cursor[N_NODES];
__device__ int   g_rowptr[N_NODES + 1];
__device__ int   g_bsums[128];
__device__ int   g_esrc[N_EDGES];             // CSR-by-dst: src per slot
__device__ float g_ewt [N_EDGES];             // CSR-by-dst: weight per slot
__device__ int   g_is64;                      // 1 if edge_index is int64
// W1^T split into bf16 hi/lo:  Wt[n][k] = W1[k][n]
__device__ __align__(16) __nv_bfloat16 g_Wt_hi[HIDDEN * N_FEAT];
__device__ __align__(16) __nv_bfloat16 g_Wt_lo[HIDDEN * N_FEAT];
// W2^T split into bf16 hi/lo:  W2t[n][k] = W2[k][n]
__device__ __align__(16) __nv_bfloat16 g_W2t_hi[N_CLASSES * HIDDEN];
__device__ __align__(16) __nv_bfloat16 g_W2t_lo[N_CLASSES * HIDDEN];

// ================= helpers ====================================================
__device__ __forceinline__ uint32_t smem_u32(const void* p) {
    uint32_t a;
    asm("{ .reg .u64 t; cvta.to.shared.u64 t, %1; cvt.u32.u64 %0, t; }"
        : "=r"(a) : "l"(p));
    return a;
}
__device__ __forceinline__ void ldsm_x4(uint32_t* r, uint32_t addr) {
    asm volatile("ldmatrix.sync.aligned.m8n8.x4.shared.b16 {%0,%1,%2,%3}, [%4];"
        : "=r"(r[0]), "=r"(r[1]), "=r"(r[2]), "=r"(r[3]) : "r"(addr));
}
__device__ __forceinline__ void mma16816(float* c, const uint32_t* a,
                                         const uint32_t* b) {
    asm volatile(
        "mma.sync.aligned.m16n8k16.row.col.f32.bf16.bf16.f32 "
        "{%0,%1,%2,%3}, {%4,%5,%6,%7}, {%8,%9}, {%0,%1,%2,%3};"
        : "+f"(c[0]), "+f"(c[1]), "+f"(c[2]), "+f"(c[3])
        : "r"(a[0]), "r"(a[1]), "r"(a[2]), "r"(a[3]), "r"(b[0]), "r"(b[1]));
}
__device__ __forceinline__ uint32_t pack_bf2(__nv_bfloat16 a, __nv_bfloat16 b) {
    __nv_bfloat162 t = __halves2bfloat162(a, b);
    uint32_t u;
    *(__nv_bfloat162*)&u = t;
    return u;
}
// split float4 -> hi/lo packed pairs
__device__ __forceinline__ void split4(float4 v, uint2* ph, uint2* pl) {
    __nv_bfloat16 h0 = __float2bfloat16(v.x);
    __nv_bfloat16 h1 = __float2bfloat16(v.y);
    __nv_bfloat16 h2 = __float2bfloat16(v.z);
    __nv_bfloat16 h3 = __float2bfloat16(v.w);
    __nv_bfloat16 l0 = __float2bfloat16(v.x - __bfloat162float(h0));
    __nv_bfloat16 l1 = __float2bfloat16(v.y - __bfloat162float(h1));
    __nv_bfloat16 l2 = __float2bfloat16(v.z - __bfloat162float(h2));
    __nv_bfloat16 l3 = __float2bfloat16(v.w - __bfloat162float(h3));
    *ph = make_uint2(pack_bf2(h0, h1), pack_bf2(h2, h3));
    *pl = make_uint2(pack_bf2(l0, l1), pack_bf2(l2, l3));
}

// ---------------- dtype probe -------------------------------------------------
__global__ void k_probe(const void* __restrict__ ei_raw) {
    const long long* p = (const long long*)ei_raw;
    int ok = 1;
    #pragma unroll
    for (int i = 0; i < 8; i++) {
        long long v = p[(size_t)i * 199999];
        if (v < 0 || v >= N_NODES) ok = 0;
    }
    g_is64 = ok;
}

__device__ __forceinline__ int load_idx(const void* ei_raw, size_t pos, int is64) {
    if (is64) return (int)((const long long*)ei_raw)[pos];
    return ((const int*)ei_raw)[pos];
}

// ---------------- CSR build ---------------------------------------------------
__global__ void k_zero_counts() {
    int i = blockIdx.x * blockDim.x + threadIdx.x;
    if (i < N_NODES) { g_counts[i] = 0; g_cursor[i] = 0; }
}

__global__ void k_hist(const void* __restrict__ ei_raw) {
    int e = blockIdx.x * blockDim.x + threadIdx.x;
    if (e < N_EDGES) {
        int dst = load_idx(ei_raw, (size_t)N_EDGES + e, g_is64);
        if ((unsigned)dst < N_NODES)
            atomicAdd(&g_counts[dst], 1);
    }
}

__global__ void k_scan1() {
    __shared__ int sh[1024];
    int tid = threadIdx.x;
    int gid = blockIdx.x * 1024 + tid;
    int v = (gid < N_NODES) ? g_counts[gid] : 0;
    sh[tid] = v;
    __syncthreads();
    #pragma unroll
    for (int off = 1; off < 1024; off <<= 1) {
        int t = (tid >= off) ? sh[tid - off] : 0;
        __syncthreads();
        sh[tid] += t;
        __syncthreads();
    }
    if (gid < N_NODES) g_rowptr[gid] = sh[tid] - v;
    if (tid == 1023) g_bsums[blockIdx.x] = sh[1023];
}

__global__ void k_scan2() {
    __shared__ int sh[128];
    int tid = threadIdx.x;
    int v = (tid < NB_SCAN) ? g_bsums[tid] : 0;
    sh[tid] = v;
    __syncthreads();
    #pragma unroll
    for (int off = 1; off < 128; off <<= 1) {
        int t = (tid >= off) ? sh[tid - off] : 0;
        __syncthreads();
        sh[tid] += t;
        __syncthreads();
    }
    if (tid < NB_SCAN) g_bsums[tid] = sh[tid] - v;
}

__global__ void k_scan3() {
    int gid = blockIdx.x * 1024 + threadIdx.x;
    if (gid < N_NODES) g_rowptr[gid] += g_bsums[blockIdx.x];
    if (gid == 0) g_rowptr[N_NODES] = N_EDGES;
}

__global__ void k_scatter(const void* __restrict__ ei_raw,
                          const float* __restrict__ ew) {
    int e = blockIdx.x * blockDim.x + threadIdx.x;
    if (e < N_EDGES) {
        int is64 = g_is64;
        int src = load_idx(ei_raw, (size_t)e, is64);
        int dst = load_idx(ei_raw, (size_t)N_EDGES + e, is64);
        if ((unsigned)dst >= N_NODES || (unsigned)src >= N_NODES) return;
        int pos = g_rowptr[dst] + atomicAdd(&g_cursor[dst], 1);
        g_esrc[pos] = src;
        g_ewt[pos]  = ew[e];
    }
}

// ---------------- weight prep: transpose + bf16 hi/lo split ------------------
__global__ void k_prepW(const float* __restrict__ W) {
    int i = blockIdx.x * blockDim.x + threadIdx.x;   // i over 512*128
    if (i < N_FEAT * HIDDEN) {
        int k = i / HIDDEN;
        int n = i % HIDDEN;
        float v = W[i];
        __nv_bfloat16 hi = __float2bfloat16(v);
        __nv_bfloat16 lo = __float2bfloat16(v - __bfloat162float(hi));
        g_Wt_hi[(size_t)n * N_FEAT + k] = hi;
        g_Wt_lo[(size_t)n * N_FEAT + k] = lo;
    }
}

__global__ void k_prepW2(const float* __restrict__ W) {
    int i = blockIdx.x * blockDim.x + threadIdx.x;   // i over 128*64
    if (i < HIDDEN * N_CLASSES) {
        int k = i / N_CLASSES;
        int n = i % N_CLASSES;
        float v = W[i];
        __nv_bfloat16 hi = __float2bfloat16(v);
        __nv_bfloat16 lo = __float2bfloat16(v - __bfloat162float(hi));
        g_W2t_hi[(size_t)n * HIDDEN + k] = hi;
        g_W2t_lo[(size_t)n * HIDDEN + k] = lo;
    }
}

// ---------------- GEMM1 (mma.sync bf16, 2-term split): h1 = x @ W1 -----------
// CTA tile 128x128, K chunks of 32, double-buffered smem, 8 warps (4x2),
// warp tile 32x64.  C = Ah*Bh + Ah*Bl + Al*Bh.
#define APAD 40                       // rows are 80B -> ldmatrix conflict-free
#define G1_STG (128 * APAD)           // elems per array stage
#define G1_SMEM_BYTES (8 * G1_STG * 2)   // 2 stages x 4 arrays = 81920 B
#define NCH (N_FEAT / 32)             // 16

__global__ __launch_bounds__(256, 2)
void k_gemm1_mma(const float* __restrict__ X) {
    extern __shared__ __nv_bfloat16 sm1[];
    // layout (elems): Ah[2*G1_STG], Al[...], Bh[...], Bl[...]
    __nv_bfloat16* sAh = sm1;
    __nv_bfloat16* sAl = sm1 + 2 * G1_STG;
    __nv_bfloat16* sBh = sm1 + 4 * G1_STG;
    __nv_bfloat16* sBl = sm1 + 6 * G1_STG;

    const int tid = threadIdx.x;
    const int wid = tid >> 5;
    const int lane = tid & 31;
    const int warp_m = wid >> 1;          // 0..3
    const int warp_n = wid & 1;           // 0..1
    const int m0 = blockIdx.x * 128;

    // staging mapping: each thread owns 1 row-half (16 elems)
    const int ar = tid >> 1;              // 0..127
    const int ac = (tid & 1) * 16;        // 0 or 16
    const bool aval = (m0 + ar) < N_NODES;
    const float* xrow = X + (size_t)(m0 + ar) * N_FEAT + ac;
    const __nv_bfloat16* bhrow = g_Wt_hi + (size_t)ar * N_FEAT + ac;
    const __nv_bfloat16* blrow = g_Wt_lo + (size_t)ar * N_FEAT + ac;
    const uint32_t stoff = (uint32_t)(ar * APAD + ac);   // elem offset in stage

    // ldmatrix element offsets (within a stage)
    const uint32_t uAh = smem_u32(sAh);
    const uint32_t uAl = smem_u32(sAl);
    const uint32_t uBh = smem_u32(sBh);
    const uint32_t uBl = smem_u32(sBl);
    const int a_row = warp_m * 32 + (lane & 7) + ((lane >> 3) & 1) * 8;
    const int a_col = ((lane >> 4) & 1) * 8;
    uint32_t oA[2];
    #pragma unroll
    for (int mt = 0; mt < 2; mt++)
        oA[mt] = (uint32_t)((a_row + mt * 16) * APAD + a_col) * 2;
    const int b_row = warp_n * 64 + (lane & 7) + ((lane >> 4) & 1) * 8;
    const int b_col = ((lane >> 3) & 1) * 8;
    uint32_t oB[4];
    #pragma unroll
    for (int p = 0; p < 4; p++)
        oB[p] = (uint32_t)((b_row + p * 16) * APAD + b_col) * 2;

    float acc[2][8][4];
    #pragma unroll
    for (int mt = 0; mt < 2; mt++)
        #pragma unroll
        for (int nt = 0; nt < 8; nt++)
            #pragma unroll
            for (int q = 0; q < 4; q++) acc[mt][nt][q] = 0.f;

    float4 av[4];
    uint4 bvh[2], bvl[2];

    // ---- prologue: stage chunk 0, prefetch chunk 1 ----
    #pragma unroll
    for (int i = 0; i < 4; i++)
        av[i] = aval ? *(const float4*)(xrow + i * 4)
                     : make_float4(0.f, 0.f, 0.f, 0.f);
    #pragma unroll
    for (int j = 0; j < 2; j++) {
        bvh[j] = *(const uint4*)(bhrow + j * 8);
        bvl[j] = *(const uint4*)(blrow + j * 8);
    }
    #pragma unroll
    for (int i = 0; i < 4; i++) {
        uint2 ph, pl;
        split4(av[i], &ph, &pl);
        *(uint2*)(sAh + stoff + i * 4) = ph;
        *(uint2*)(sAl + stoff + i * 4) = pl;
    }
    #pragma unroll
    for (int j = 0; j < 2; j++) {
        *(uint4*)(sBh + stoff + j * 8) = bvh[j];
        *(uint4*)(sBl + stoff + j * 8) = bvl[j];
    }
    #pragma unroll
    for (int i = 0; i < 4; i++)
        av[i] = aval ? *(const float4*)(xrow + 32 + i * 4)
                     : make_float4(0.f, 0.f, 0.f, 0.f);
    #pragma unroll
    for (int j = 0; j < 2; j++) {
        bvh[j] = *(const uint4*)(bhrow + 32 + j * 8);
        bvl[j] = *(const uint4*)(blrow + 32 + j * 8);
    }
    __syncthreads();

    for (int kc = 0; kc < NCH; kc++) {
        const uint32_t cur = (kc & 1) * (uint32_t)G1_STG;
        // stage chunk kc+1 into other stage (data already in regs)
        if (kc + 1 < NCH) {
            const uint32_t nxt = ((kc + 1) & 1) * (uint32_t)G1_STG;
            #pragma unroll
            for (int i = 0; i < 4; i++) {
                uint2 ph, pl;
                split4(av[i], &ph, &pl);
                *(uint2*)(sAh + nxt + stoff + i * 4) = ph;
                *(uint2*)(sAl + nxt + stoff + i * 4) = pl;
            }
            #pragma unroll
            for (int j = 0; j < 2; j++) {
                *(uint4*)(sBh + nxt + stoff + j * 8) = bvh[j];
                *(uint4*)(sBl + nxt + stoff + j * 8) = bvl[j];
            }
        }
        // prefetch chunk kc+2
        if (kc + 2 < NCH) {
            #pragma unroll
            for (int i = 0; i < 4; i++)
                av[i] = aval ? *(const float4*)(xrow + (kc + 2) * 32 + i * 4)
                             : make_float4(0.f, 0.f, 0.f, 0.f);
            #pragma unroll
            for (int j = 0; j < 2; j++) {
                bvh[j] = *(const uint4*)(bhrow + (kc + 2) * 32 + j * 8);
                bvl[j] = *(const uint4*)(blrow + (kc + 2) * 32 + j * 8);
            }
        }
        // MMA on stage cur
        const uint32_t c2 = cur * 2;   // byte offset of stage
        #pragma unroll
        for (int ks = 0; ks < 2; ks++) {
            uint32_t Ah0[4], Ah1[4], Al0[4], Al1[4];
            ldsm_x4(Ah0, uAh + c2 + oA[0] + ks * 32);
            ldsm_x4(Ah1, uAh + c2 + oA[1] + ks * 32);
            ldsm_x4(Al0, uAl + c2 + oA[0] + ks * 32);
            ldsm_x4(Al1, uAl + c2 + oA[1] + ks * 32);
            #pragma unroll
            for (int p = 0; p < 4; p++) {
                uint32_t Bh[4], Bl[4];
                ldsm_x4(Bh, uBh + c2 + oB[p] + ks * 32);
                ldsm_x4(Bl, uBl + c2 + oB[p] + ks * 32);
                mma16816(acc[0][2 * p + 0], Ah0, Bh + 0);
                mma16816(acc[0][2 * p + 1], Ah0, Bh + 2);
                mma16816(acc[1][2 * p + 0], Ah1, Bh + 0);
                mma16816(acc[1][2 * p + 1], Ah1, Bh + 2);
                mma16816(acc[0][2 * p + 0], Al0, Bh + 0);
                mma16816(acc[0][2 * p + 1], Al0, Bh + 2);
                mma16816(acc[1][2 * p + 0], Al1, Bh + 0);
                mma16816(acc[1][2 * p + 1], Al1, Bh + 2);
                mma16816(acc[0][2 * p + 0], Ah0, Bl + 0);
                mma16816(acc[0][2 * p + 1], Ah0, Bl + 2);
                mma16816(acc[1][2 * p + 0], Ah1, Bl + 0);
                mma16816(acc[1][2 * p + 1], Ah1, Bl + 2);
            }
        }
        __syncthreads();
    }

    // --- epilogue: acc -> g_h1 ---
    #pragma unroll
    for (int mt = 0; mt < 2; mt++) {
        int row = m0 + warp_m * 32 + mt * 16 + (lane >> 2);
        #pragma unroll
        for (int nt = 0; nt < 8; nt++) {
            int col = warp_n * 64 + nt * 8 + (lane & 3) * 2;
            if (row < N_NODES)
                *(float2*)&g_h1[(size_t)row * HIDDEN + col] =
                    make_float2(acc[mt][nt][0], acc[mt][nt][1]);
            if (row + 8 < N_NODES)
                *(float2*)&g_h1[(size_t)(row + 8) * HIDDEN + col] =
                    make_float2(acc[mt][nt][2], acc[mt][nt][3]);
        }
    }
}

// ---------------- GEMM2 (mma.sync bf16 split): h2 = h @ W2 -------------------
// CTA tile 128x64, K=128 staged once. 8 warps (4x2), warp tile 32x32.
#define G2PAD 136
#define G2_A (128 * G2PAD)            // elems per A array
#define G2_B (64 * G2PAD)             // elems per B array
#define G2_SMEM_BYTES ((2 * G2_A + 2 * G2_B) * 2)   // 104448 B

__global__ __launch_bounds__(256, 2)
void k_gemm2_mma() {
    extern __shared__ __nv_bfloat16 sm2[];
    __nv_bfloat16* sAh = sm2;
    __nv_bfloat16* sAl = sm2 + G2_A;
    __nv_bfloat16* sBh = sm2 + 2 * G2_A;
    __nv_bfloat16* sBl = sm2 + 2 * G2_A + G2_B;

    const int tid = threadIdx.x;
    const int wid = tid >> 5;
    const int lane = tid & 31;
    const int warp_m = wid >> 1;          // 0..3
    const int warp_n = wid & 1;           // 0..1
    const int m0 = blockIdx.x * 128;

    // --- stage A: 128 rows x 128 cols fp32 -> split ---
    {
        const int ar = tid >> 1;
        const int ac = (tid & 1) * 64;
        const bool aval = (m0 + ar) < N_NODES;
        const float* hrow = g_h + (size_t)(m0 + ar) * HIDDEN + ac;
        #pragma unroll
        for (int i = 0; i < 16; i++) {
            float4 v = aval ? *(const float4*)(hrow + i * 4)
                            : make_float4(0.f, 0.f, 0.f, 0.f);
            uint2 ph, pl;
            split4(v, &ph, &pl);
            *(uint2*)(sAh + ar * G2PAD + ac + i * 4) = ph;
            *(uint2*)(sAl + ar * G2PAD + ac + i * 4) = pl;
        }
    }
    // --- stage B: 64 rows x 128 cols prepped bf16 ---
    {
        const int br = tid >> 2;          // 0..63
        const int bc = (tid & 3) * 32;
        const __nv_bfloat16* bh = g_W2t_hi + (size_t)br * HIDDEN + bc;
        const __nv_bfloat16* bl = g_W2t_lo + (size_t)br * HIDDEN + bc;
        #pragma unroll
        for (int j = 0; j < 4; j++) {
            *(uint4*)(sBh + br * G2PAD + bc + j * 8) = *(const uint4*)(bh + j * 8);
            *(uint4*)(sBl + br * G2PAD + bc + j * 8) = *(const uint4*)(bl + j * 8);
        }
    }
    __syncthreads();

    const uint32_t uAh = smem_u32(sAh);
    const uint32_t uAl = smem_u32(sAl);
    const uint32_t uBh = smem_u32(sBh);
    const uint32_t uBl = smem_u32(sBl);
    const int a_row = warp_m * 32 + (lane & 7) + ((lane >> 3) & 1) * 8;
    const int a_col = ((lane >> 4) & 1) * 8;
    uint32_t adA[2];
    #pragma unroll
    for (int mt = 0; mt < 2; mt++)
        adA[mt] = (uint32_t)((a_row + mt * 16) * G2PAD + a_col) * 2;
    const int b_row = warp_n * 32 + (lane & 7) + ((lane >> 4) & 1) * 8;
    const int b_col = ((lane >> 3) & 1) * 8;
    uint32_t adB[2];
    #pragma unroll
    for (int p = 0; p < 2; p++)
        adB[p] = (uint32_t)((b_row + p * 16) * G2PAD + b_col) * 2;

    float acc[2][4][4];
    #pragma unroll
    for (int mt = 0; mt < 2; mt++)
        #pragma unroll
        for (int nt = 0; nt < 4; nt++)
            #pragma unroll
            for (int q = 0; q < 4; q++) acc[mt][nt][q] = 0.f;

    #pragma unroll
    for (int ks = 0; ks < 8; ks++) {
        uint32_t Ah0[4], Ah1[4], Al0[4], Al1[4];
        ldsm_x4(Ah0, uAh + adA[0] + ks * 32);
        ldsm_x4(Ah1, uAh + adA[1] + ks * 32);
        ldsm_x4(Al0, uAl + adA[0] + ks * 32);
        ldsm_x4(Al1, uAl + adA[1] + ks * 32);
        #pragma unroll
        for (int p = 0; p < 2; p++) {
            uint32_t Bh[4], Bl[4];
            ldsm_x4(Bh, uBh + adB[p] + ks * 32);
            ldsm_x4(Bl, uBl + adB[p] + ks * 32);
            mma16816(acc[0][2 * p + 0], Ah0, Bh + 0);
            mma16816(acc[0][2 * p + 1], Ah0, Bh + 2);
            mma16816(acc[1][2 * p + 0], Ah1, Bh + 0);
            mma16816(acc[1][2 * p + 1], Ah1, Bh + 2);
            mma16816(acc[0][2 * p + 0], Al0, Bh + 0);
            mma16816(acc[0][2 * p + 1], Al0, Bh + 2);
            mma16816(acc[1][2 * p + 0], Al1, Bh + 0);
            mma16816(acc[1][2 * p + 1], Al1, Bh + 2);
            mma16816(acc[0][2 * p + 0], Ah0, Bl + 0);
            mma16816(acc[0][2 * p + 1], Ah0, Bl + 2);
            mma16816(acc[1][2 * p + 0], Ah1, Bl + 0);
            mma16816(acc[1][2 * p + 1], Ah1, Bl + 2);
        }
    }

    #pragma unroll
    for (int mt = 0; mt < 2; mt++) {
        int row = m0 + warp_m * 32 + mt * 16 + (lane >> 2);
        #pragma unroll
        for (int nt = 0; nt < 4; nt++) {
            int col = warp_n * 32 + nt * 8 + (lane & 3) * 2;
            if (row < N_NODES)
                *(float2*)&g_h2[(size_t)row * N_CLASSES + col] =
                    make_float2(acc[mt][nt][0], acc[mt][nt][1]);
            if (row + 8 < N_NODES)
                *(float2*)&g_h2[(size_t)(row + 8) * N_CLASSES + col] =
                    make_float2(acc[mt][nt][2], acc[mt][nt][3]);
        }
    }
}

// ---------------- prop1: h = relu(segment_sum(w*h1[src]) + b1) ---------------
__global__ __launch_bounds__(128)
void k_prop1(const float* __restrict__ b1) {
    __shared__ int   ss[128];
    __shared__ float sw[128];
    const int n = blockIdx.x;
    const int f = threadIdx.x;
    float a0 = b1[f], a1 = 0.f, a2 = 0.f, a3 = 0.f;
    const int beg = g_rowptr[n];
    const int end = g_rowptr[n + 1];
    for (int base = beg; base < end; base += 128) {
        int cnt = min(128, end - base);
        if (f < cnt) { ss[f] = g_esrc[base + f]; sw[f] = g_ewt[base + f]; }
        __syncthreads();
        int i = 0;
        for (; i + 4 <= cnt; i += 4) {
            float v0 = g_h1[(size_t)ss[i + 0] * HIDDEN + f];
            float v1 = g_h1[(size_t)ss[i + 1] * HIDDEN + f];
            float v2 = g_h1[(size_t)ss[i + 2] * HIDDEN + f];
            float v3 = g_h1[(size_t)ss[i + 3] * HIDDEN + f];
            a0 = fmaf(sw[i + 0], v0, a0);
            a1 = fmaf(sw[i + 1], v1, a1);
            a2 = fmaf(sw[i + 2], v2, a2);
            a3 = fmaf(sw[i + 3], v3, a3);
        }
        for (; i < cnt; i++)
            a0 = fmaf(sw[i], g_h1[(size_t)ss[i] * HIDDEN + f], a0);
        __syncthreads();
    }
    float acc = (a0 + a1) + (a2 + a3);
    g_h[(size_t)n * HIDDEN + f] = fmaxf(acc, 0.f);
}

// ---------------- prop2: out = segment_sum(w*h2[src]) + b2 -------------------
__global__ __launch_bounds__(64)
void k_prop2(const float* __restrict__ b2, float* __restrict__ out) {
    __shared__ int   ss[64];
    __shared__ float sw[64];
    const int n = blockIdx.x;
    const int f = threadIdx.x;
    float a0 = b2[f], a1 = 0.f, a2 = 0.f, a3 = 0.f;
    const int beg = g_rowptr[n];
    const int end = g_rowptr[n + 1];
    for (int base = beg; base < end; base += 64) {
        int cnt = min(64, end - base);
        if (f < cnt) { ss[f] = g_esrc[base + f]; sw[f] = g_ewt[base + f]; }
        __syncthreads();
        int i = 0;
        for (; i + 4 <= cnt; i += 4) {
            float v0 = g_h2[(size_t)ss[i + 0] * N_CLASSES + f];
            float v1 = g_h2[(size_t)ss[i + 1] * N_CLASSES + f];
            float v2 = g_h2[(size_t)ss[i + 2] * N_CLASSES + f];
            float v3 = g_h2[(size_t)ss[i + 3] * N_CLASSES + f];
            a0 = fmaf(sw[i + 0], v0, a0);
            a1 = fmaf(sw[i + 1], v1, a1);
            a2 = fmaf(sw[i + 2], v2, a2);
            a3 = fmaf(sw[i + 3], v3, a3);
        }
        for (; i < cnt; i++)
            a0 = fmaf(sw[i], g_h2[(size_t)ss[i] * N_CLASSES + f], a0);
        __syncthreads();
    }
    out[(size_t)n * N_CLASSES + f] = (a0 + a1) + (a2 + a3);
}

// ---------------- launch ------------------------------------------------------
extern "C" void kernel_launch(void* const* d_in, const int* in_sizes, int n_in,
                              void* d_out, int out_size) {
    const float* x  = (const float*)d_in[0];
    const void*  ei = d_in[1];
    const float* ew = (const float*)d_in[2];
    const float* W1 = (const float*)d_in[3];
    const float* b1 = (const float*)d_in[4];
    const float* W2 = (const float*)d_in[5];
    const float* b2 = (const float*)d_in[6];
    float* out = (float*)d_out;

    k_probe<<<1, 1>>>(ei);
    k_zero_counts<<<(N_NODES + 255) / 256, 256>>>();
    k_hist<<<(N_EDGES + 255) / 256, 256>>>(ei);
    k_scan1<<<NB_SCAN, 1024>>>();
    k_scan2<<<1, 128>>>();
    k_scan3<<<NB_SCAN, 1024>>>();
    k_scatter<<<(N_EDGES + 255) / 256, 256>>>(ei, ew);

    k_prepW<<<(N_FEAT * HIDDEN + 255) / 256, 256>>>(W1);
    k_prepW2<<<(HIDDEN * N_CLASSES + 255) / 256, 256>>>(W2);

    cudaFuncSetAttribute(k_gemm1_mma, cudaFuncAttributeMaxDynamicSharedMemorySize,
                         G1_SMEM_BYTES);
    k_gemm1_mma<<<(N_NODES + 127) / 128, 256, G1_SMEM_BYTES>>>(x);
    k_prop1<<<N_NODES, 128>>>(b1);
    cudaFuncSetAttribute(k_gemm2_mma, cudaFuncAttributeMaxDynamicSharedMemorySize,
                         G2_SMEM_BYTES);
    k_gemm2_mma<<<(N_NODES + 127) / 128, 256, G2_SMEM_BYTES>>>();
    k_prop2<<<N_NODES, 64>>>(b2, out);
}

// round 12
// speedup vs baseline: 1.1377x; 1.1377x over previous
#include <cuda_runtime.h>
#include <cuda_bf16.h>
#include <cstdint>

#define N_NODES   100000
#define N_EDGES   1600000
#define N_FEAT    512
#define HIDDEN    128
#define N_CLASSES 64

#define NB_SCAN   ((N_NODES + 1023) / 1024)   // 98

// ---------------- scratch (static device globals; no allocation) -------------
__device__ float g_h1[N_NODES * HIDDEN];      // x @ W1
__device__ float g_h [N_NODES * HIDDEN];      // relu(prop1 + b1)
__device__ float g_h2[N_NODES * N_CLASSES];   // h @ W2
__device__ int   g_counts[N_NODES];
__device__ int   g_cursor[N_NODES];
__device__ int   g_rowptr[N_NODES + 1];
__device__ int   g_bsums[128];
__device__ int   g_esrc[N_EDGES];             // CSR-by-dst: src per slot
__device__ float g_ewt [N_EDGES];             // CSR-by-dst: weight per slot
__device__ int   g_is64;                      // 1 if edge_index is int64
// W1^T split into bf16 hi/lo:  Wt[n][k] = W1[k][n]
__device__ __align__(16) __nv_bfloat16 g_Wt_hi[HIDDEN * N_FEAT];
__device__ __align__(16) __nv_bfloat16 g_Wt_lo[HIDDEN * N_FEAT];

// ================= helpers ====================================================
__device__ __forceinline__ uint32_t smem_u32(const void* p) {
    uint32_t a;
    asm("{ .reg .u64 t; cvta.to.shared.u64 t, %1; cvt.u32.u64 %0, t; }"
        : "=r"(a) : "l"(p));
    return a;
}
__device__ __forceinline__ void ldsm_x4(uint32_t* r, uint32_t addr) {
    asm volatile("ldmatrix.sync.aligned.m8n8.x4.shared.b16 {%0,%1,%2,%3}, [%4];"
        : "=r"(r[0]), "=r"(r[1]), "=r"(r[2]), "=r"(r[3]) : "r"(addr));
}
__device__ __forceinline__ void mma16816(float* c, const uint32_t* a,
                                         const uint32_t* b) {
    asm volatile(
        "mma.sync.aligned.m16n8k16.row.col.f32.bf16.bf16.f32 "
        "{%0,%1,%2,%3}, {%4,%5,%6,%7}, {%8,%9}, {%0,%1,%2,%3};"
        : "+f"(c[0]), "+f"(c[1]), "+f"(c[2]), "+f"(c[3])
        : "r"(a[0]), "r"(a[1]), "r"(a[2]), "r"(a[3]), "r"(b[0]), "r"(b[1]));
}
__device__ __forceinline__ uint32_t pack_bf2(__nv_bfloat16 a, __nv_bfloat16 b) {
    __nv_bfloat162 t = __halves2bfloat162(a, b);
    uint32_t u;
    *(__nv_bfloat162*)&u = t;
    return u;
}

// ---------------- dtype probe -------------------------------------------------
__global__ void k_probe(const void* __restrict__ ei_raw) {
    const long long* p = (const long long*)ei_raw;
    int ok = 1;
    #pragma unroll
    for (int i = 0; i < 8; i++) {
        long long v = p[(size_t)i * 199999];
        if (v < 0 || v >= N_NODES) ok = 0;
    }
    g_is64 = ok;
}

__device__ __forceinline__ int load_idx(const void* ei_raw, size_t pos, int is64) {
    if (is64) return (int)((const long long*)ei_raw)[pos];
    return ((const int*)ei_raw)[pos];
}

// ---------------- CSR build ---------------------------------------------------
__global__ void k_zero_counts() {
    int i = blockIdx.x * blockDim.x + threadIdx.x;
    if (i < N_NODES) { g_counts[i] = 0; g_cursor[i] = 0; }
}

__global__ void k_hist(const void* __restrict__ ei_raw) {
    int e = blockIdx.x * blockDim.x + threadIdx.x;
    if (e < N_EDGES) {
        int dst = load_idx(ei_raw, (size_t)N_EDGES + e, g_is64);
        if ((unsigned)dst < N_NODES)
            atomicAdd(&g_counts[dst], 1);
    }
}

__global__ void k_scan1() {
    __shared__ int sh[1024];
    int tid = threadIdx.x;
    int gid = blockIdx.x * 1024 + tid;
    int v = (gid < N_NODES) ? g_counts[gid] : 0;
    sh[tid] = v;
    __syncthreads();
    #pragma unroll
    for (int off = 1; off < 1024; off <<= 1) {
        int t = (tid >= off) ? sh[tid - off] : 0;
        __syncthreads();
        sh[tid] += t;
        __syncthreads();
    }
    if (gid < N_NODES) g_rowptr[gid] = sh[tid] - v;
    if (tid == 1023) g_bsums[blockIdx.x] = sh[1023];
}

__global__ void k_scan2() {
    __shared__ int sh[128];
    int tid = threadIdx.x;
    int v = (tid < NB_SCAN) ? g_bsums[tid] : 0;
    sh[tid] = v;
    __syncthreads();
    #pragma unroll
    for (int off = 1; off < 128; off <<= 1) {
        int t = (tid >= off) ? sh[tid - off] : 0;
        __syncthreads();
        sh[tid] += t;
        __syncthreads();
    }
    if (tid < NB_SCAN) g_bsums[tid] = sh[tid] - v;
}

__global__ void k_scan3() {
    int gid = blockIdx.x * 1024 + threadIdx.x;
    if (gid < N_NODES) g_rowptr[gid] += g_bsums[blockIdx.x];
    if (gid == 0) g_rowptr[N_NODES] = N_EDGES;
}

__global__ void k_scatter(const void* __restrict__ ei_raw,
                          const float* __restrict__ ew) {
    int e = blockIdx.x * blockDim.x + threadIdx.x;
    if (e < N_EDGES) {
        int is64 = g_is64;
        int src = load_idx(ei_raw, (size_t)e, is64);
        int dst = load_idx(ei_raw, (size_t)N_EDGES + e, is64);
        if ((unsigned)dst >= N_NODES || (unsigned)src >= N_NODES) return;
        int pos = g_rowptr[dst] + atomicAdd(&g_cursor[dst], 1);
        g_esrc[pos] = src;
        g_ewt[pos]  = ew[e];
    }
}

// ---------------- W1 prep: transpose + bf16 hi/lo split ----------------------
__global__ void k_prepW(const float* __restrict__ W) {
    int i = blockIdx.x * blockDim.x + threadIdx.x;   // i over 512*128
    if (i < N_FEAT * HIDDEN) {
        int k = i / HIDDEN;
        int n = i % HIDDEN;
        float v = W[i];
        __nv_bfloat16 hi = __float2bfloat16(v);
        __nv_bfloat16 lo = __float2bfloat16(v - __bfloat162float(hi));
        g_Wt_hi[(size_t)n * N_FEAT + k] = hi;
        g_Wt_lo[(size_t)n * N_FEAT + k] = lo;
    }
}

// ---------------- GEMM1 (mma.sync bf16, 2-term split): h1 = x @ W1 -----------
// CTA tile 128x128, K chunks of 32, 8 warps (4x2), warp tile 32x64.
// D[m][n] = sum_k A[m][k] * B[n][k];  C = Ah*Bh + Ah*Bl + Al*Bh.
#define APAD 40   // 32 + 8 pad, rows are 80B -> ldmatrix conflict-free

__global__ __launch_bounds__(256, 2)
void k_gemm1_mma(const float* __restrict__ X) {
    __shared__ __align__(16) __nv_bfloat16 sAh[128][APAD];
    __shared__ __align__(16) __nv_bfloat16 sAl[128][APAD];
    __shared__ __align__(16) __nv_bfloat16 sBh[128][APAD];
    __shared__ __align__(16) __nv_bfloat16 sBl[128][APAD];

    const int tid = threadIdx.x;
    const int wid = tid >> 5;
    const int lane = tid & 31;
    const int warp_m = wid >> 1;          // 0..3
    const int warp_n = wid & 1;           // 0..1
    const int m0 = blockIdx.x * 128;

    // staging mapping: each thread owns 1 row-half (16 elems)
    const int ar = tid >> 1;              // 0..127
    const int ac = (tid & 1) * 16;        // 0 or 16
    const bool aval = (m0 + ar) < N_NODES;
    const float* xrow = X + (size_t)(m0 + ar) * N_FEAT + ac;
    const __nv_bfloat16* bhrow = g_Wt_hi + (size_t)ar * N_FEAT + ac;
    const __nv_bfloat16* blrow = g_Wt_lo + (size_t)ar * N_FEAT + ac;

    // ldmatrix addresses
    const uint32_t uAh = smem_u32(&sAh[0][0]);
    const uint32_t uAl = smem_u32(&sAl[0][0]);
    const uint32_t uBh = smem_u32(&sBh[0][0]);
    const uint32_t uBl = smem_u32(&sBl[0][0]);
    const int a_row = warp_m * 32 + (lane & 7) + ((lane >> 3) & 1) * 8;
    const int a_col = ((lane >> 4) & 1) * 8;
    uint32_t adAh[2], adAl[2];
    #pragma unroll
    for (int mt = 0; mt < 2; mt++) {
        uint32_t off = (uint32_t)((a_row + mt * 16) * APAD + a_col) * 2;
        adAh[mt] = uAh + off;
        adAl[mt] = uAl + off;
    }
    const int b_row = warp_n * 64 + (lane & 7) + ((lane >> 4) & 1) * 8;
    const int b_col = ((lane >> 3) & 1) * 8;
    uint32_t adBh[4], adBl[4];
    #pragma unroll
    for (int p = 0; p < 4; p++) {
        uint32_t off = (uint32_t)((b_row + p * 16) * APAD + b_col) * 2;
        adBh[p] = uBh + off;
        adBl[p] = uBl + off;
    }

    float acc[2][8][4];
    #pragma unroll
    for (int mt = 0; mt < 2; mt++)
        #pragma unroll
        for (int nt = 0; nt < 8; nt++)
            #pragma unroll
            for (int q = 0; q < 4; q++) acc[mt][nt][q] = 0.f;

    // prefetch A chunk 0
    float4 av[4];
    #pragma unroll
    for (int i = 0; i < 4; i++)
        av[i] = aval ? *(const float4*)(xrow + i * 4)
                     : make_float4(0.f, 0.f, 0.f, 0.f);

    for (int kc = 0; kc < N_FEAT / 32; kc++) {
        __syncthreads();     // previous chunk consumed
        // --- STS A (split to hi/lo) ---
        #pragma unroll
        for (int i = 0; i < 4; i++) {
            float4 v = av[i];
            __nv_bfloat16 h0 = __float2bfloat16(v.x);
            __nv_bfloat16 h1 = __float2bfloat16(v.y);
            __nv_bfloat16 h2 = __float2bfloat16(v.z);
            __nv_bfloat16 h3 = __float2bfloat16(v.w);
            __nv_bfloat16 l0 = __float2bfloat16(v.x - __bfloat162float(h0));
            __nv_bfloat16 l1 = __float2bfloat16(v.y - __bfloat162float(h1));
            __nv_bfloat16 l2 = __float2bfloat16(v.z - __bfloat162float(h2));
            __nv_bfloat16 l3 = __float2bfloat16(v.w - __bfloat162float(h3));
            *(uint2*)&sAh[ar][ac + i * 4] =
                make_uint2(pack_bf2(h0, h1), pack_bf2(h2, h3));
            *(uint2*)&sAl[ar][ac + i * 4] =
                make_uint2(pack_bf2(l0, l1), pack_bf2(l2, l3));
        }
        // --- LDG+STS B (prepped bf16, L2-resident) ---
        #pragma unroll
        for (int j = 0; j < 2; j++) {
            *(uint4*)&sBh[ar][ac + j * 8] =
                *(const uint4*)(bhrow + kc * 32 + j * 8);
            *(uint4*)&sBl[ar][ac + j * 8] =
                *(const uint4*)(blrow + kc * 32 + j * 8);
        }
        __syncthreads();

        // prefetch next A chunk (overlaps with mma below)
        if (kc + 1 < N_FEAT / 32) {
            #pragma unroll
            for (int i = 0; i < 4; i++)
                av[i] = aval ? *(const float4*)(xrow + (kc + 1) * 32 + i * 4)
                             : make_float4(0.f, 0.f, 0.f, 0.f);
        }

        // --- MMA over the 2 k-steps of this chunk ---
        #pragma unroll
        for (int ks = 0; ks < 2; ks++) {
            uint32_t Ah0[4], Ah1[4], Al0[4], Al1[4];
            ldsm_x4(Ah0, adAh[0] + ks * 32);
            ldsm_x4(Ah1, adAh[1] + ks * 32);
            ldsm_x4(Al0, adAl[0] + ks * 32);
            ldsm_x4(Al1, adAl[1] + ks * 32);
            #pragma unroll
            for (int p = 0; p < 4; p++) {
                uint32_t Bh[4], Bl[4];
                ldsm_x4(Bh, adBh[p] + ks * 32);
                ldsm_x4(Bl, adBl[p] + ks * 32);
                // Ah*Bh
                mma16816(acc[0][2 * p + 0], Ah0, Bh + 0);
                mma16816(acc[0][2 * p + 1], Ah0, Bh + 2);
                mma16816(acc[1][2 * p + 0], Ah1, Bh + 0);
                mma16816(acc[1][2 * p + 1], Ah1, Bh + 2);
                // Al*Bh
                mma16816(acc[0][2 * p + 0], Al0, Bh + 0);
                mma16816(acc[0][2 * p + 1], Al0, Bh + 2);
                mma16816(acc[1][2 * p + 0], Al1, Bh + 0);
                mma16816(acc[1][2 * p + 1], Al1, Bh + 2);
                // Ah*Bl
                mma16816(acc[0][2 * p + 0], Ah0, Bl + 0);
                mma16816(acc[0][2 * p + 1], Ah0, Bl + 2);
                mma16816(acc[1][2 * p + 0], Ah1, Bl + 0);
                mma16816(acc[1][2 * p + 1], Ah1, Bl + 2);
            }
        }
    }

    // --- epilogue: acc -> g_h1 ---
    #pragma unroll
    for (int mt = 0; mt < 2; mt++) {
        int row = m0 + warp_m * 32 + mt * 16 + (lane >> 2);
        #pragma unroll
        for (int nt = 0; nt < 8; nt++) {
            int col = warp_n * 64 + nt * 8 + (lane & 3) * 2;
            if (row < N_NODES)
                *(float2*)&g_h1[(size_t)row * HIDDEN + col] =
                    make_float2(acc[mt][nt][0], acc[mt][nt][1]);
            if (row + 8 < N_NODES)
                *(float2*)&g_h1[(size_t)(row + 8) * HIDDEN + col] =
                    make_float2(acc[mt][nt][2], acc[mt][nt][3]);
        }
    }
}

// ---------------- prop1: h = relu(segment_sum(w*h1[src]) + b1) ---------------
__global__ __launch_bounds__(128)
void k_prop1(const float* __restrict__ b1) {
    __shared__ int   ss[128];
    __shared__ float sw[128];
    const int n = blockIdx.x;
    const int f = threadIdx.x;
    float a0 = b1[f], a1 = 0.f, a2 = 0.f, a3 = 0.f;
    const int beg = g_rowptr[n];
    const int end = g_rowptr[n + 1];
    for (int base = beg; base < end; base += 128) {
        int cnt = min(128, end - base);
        if (f < cnt) { ss[f] = g_esrc[base + f]; sw[f] = g_ewt[base + f]; }
        __syncthreads();
        int i = 0;
        for (; i + 4 <= cnt; i += 4) {
            float v0 = g_h1[(size_t)ss[i + 0] * HIDDEN + f];
            float v1 = g_h1[(size_t)ss[i + 1] * HIDDEN + f];
            float v2 = g_h1[(size_t)ss[i + 2] * HIDDEN + f];
            float v3 = g_h1[(size_t)ss[i + 3] * HIDDEN + f];
            a0 = fmaf(sw[i + 0], v0, a0);
            a1 = fmaf(sw[i + 1], v1, a1);
            a2 = fmaf(sw[i + 2], v2, a2);
            a3 = fmaf(sw[i + 3], v3, a3);
        }
        for (; i < cnt; i++)
            a0 = fmaf(sw[i], g_h1[(size_t)ss[i] * HIDDEN + f], a0);
        __syncthreads();
    }
    float acc = (a0 + a1) + (a2 + a3);
    g_h[(size_t)n * HIDDEN + f] = fmaxf(acc, 0.f);
}

// ---------------- GEMM2: h2[M,64] = h[M,128] @ W2[128,64] --------------------
__global__ __launch_bounds__(256)
void k_gemm2(const float* __restrict__ W) {
    __shared__ float As[16][128 + 4];
    __shared__ float Bs[16][64];
    const int tid = threadIdx.x;
    const int tx  = tid & 15;
    const int ty  = tid >> 4;
    const int m0  = blockIdx.x * 128;

    const int arow  = tid >> 2;
    const int acol4 = (tid & 3) * 4;
    const int brow  = tid >> 4;
    const int bcol4 = (tid & 15) * 4;

    float acc[8][4];
    #pragma unroll
    for (int i = 0; i < 8; i++)
        #pragma unroll
        for (int j = 0; j < 4; j++) acc[i][j] = 0.f;

    for (int k0 = 0; k0 < HIDDEN; k0 += 16) {
        #pragma unroll
        for (int h = 0; h < 2; h++) {
            int r = arow + h * 64;
            float4 v = make_float4(0.f, 0.f, 0.f, 0.f);
            if (m0 + r < N_NODES)
                v = *(const float4*)&g_h[(size_t)(m0 + r) * HIDDEN + k0 + acol4];
            As[acol4 + 0][r] = v.x; As[acol4 + 1][r] = v.y;
            As[acol4 + 2][r] = v.z; As[acol4 + 3][r] = v.w;
        }
        *(float4*)&Bs[brow][bcol4] =
            *(const float4*)&W[(size_t)(k0 + brow) * N_CLASSES + bcol4];
        __syncthreads();
        #pragma unroll
        for (int k = 0; k < 16; k++) {
            float a[8], b[4];
            #pragma unroll
            for (int i = 0; i < 8; i++) a[i] = As[k][ty + 16 * i];
            #pragma unroll
            for (int j = 0; j < 4; j++) b[j] = Bs[k][tx + 16 * j];
            #pragma unroll
            for (int i = 0; i < 8; i++)
                #pragma unroll
                for (int j = 0; j < 4; j++)
                    acc[i][j] = fmaf(a[i], b[j], acc[i][j]);
        }
        __syncthreads();
    }
    #pragma unroll
    for (int i = 0; i < 8; i++) {
        int m = m0 + ty + 16 * i;
        if (m < N_NODES) {
            #pragma unroll
            for (int j = 0; j < 4; j++)
                g_h2[(size_t)m * N_CLASSES + tx + 16 * j] = acc[i][j];
        }
    }
}

// ---------------- prop2: out = segment_sum(w*h2[src]) + b2 -------------------
__global__ __launch_bounds__(64)
void k_prop2(const float* __restrict__ b2, float* __restrict__ out) {
    __shared__ int   ss[64];
    __shared__ float sw[64];
    const int n = blockIdx.x;
    const int f = threadIdx.x;
    float a0 = b2[f], a1 = 0.f, a2 = 0.f, a3 = 0.f;
    const int beg = g_rowptr[n];
    const int end = g_rowptr[n + 1];
    for (int base = beg; base < end; base += 64) {
        int cnt = min(64, end - base);
        if (f < cnt) { ss[f] = g_esrc[base + f]; sw[f] = g_ewt[base + f]; }
        __syncthreads();
        int i = 0;
        for (; i + 4 <= cnt; i += 4) {
            float v0 = g_h2[(size_t)ss[i + 0] * N_CLASSES + f];
            float v1 = g_h2[(size_t)ss[i + 1] * N_CLASSES + f];
            float v2 = g_h2[(size_t)ss[i + 2] * N_CLASSES + f];
            float v3 = g_h2[(size_t)ss[i + 3] * N_CLASSES + f];
            a0 = fmaf(sw[i + 0], v0, a0);
            a1 = fmaf(sw[i + 1], v1, a1);
            a2 = fmaf(sw[i + 2], v2, a2);
            a3 = fmaf(sw[i + 3], v3, a3);
        }
        for (; i < cnt; i++)
            a0 = fmaf(sw[i], g_h2[(size_t)ss[i] * N_CLASSES + f], a0);
        __syncthreads();
    }
    out[(size_t)n * N_CLASSES + f] = (a0 + a1) + (a2 + a3);
}

// ---------------- launch ------------------------------------------------------
extern "C" void kernel_launch(void* const* d_in, const int* in_sizes, int n_in,
                              void* d_out, int out_size) {
    const float* x  = (const float*)d_in[0];
    const void*  ei = d_in[1];
    const float* ew = (const float*)d_in[2];
    const float* W1 = (const float*)d_in[3];
    const float* b1 = (const float*)d_in[4];
    const float* W2 = (const float*)d_in[5];
    const float* b2 = (const float*)d_in[6];
    float* out = (float*)d_out;

    // lazy host-side stream/event objects (no device memory involved)
    static cudaStream_t s_csr = nullptr;
    static cudaEvent_t  e_fork = nullptr, e_join = nullptr;
    if (s_csr == nullptr) {
        cudaStreamCreateWithFlags(&s_csr, cudaStreamNonBlocking);
        cudaEventCreateWithFlags(&e_fork, cudaEventDisableTiming);
        cudaEventCreateWithFlags(&e_join, cudaEventDisableTiming);
    }

    // fork: CSR chain on s_csr, GEMM1 chain on the capture (default) stream
    cudaEventRecord(e_fork, 0);
    cudaStreamWaitEvent(s_csr, e_fork, 0);

    // --- branch B (CSR build) on s_csr ---
    k_probe<<<1, 1, 0, s_csr>>>(ei);
    k_zero_counts<<<(N_NODES + 255) / 256, 256, 0, s_csr>>>();
    k_hist<<<(N_EDGES + 255) / 256, 256, 0, s_csr>>>(ei);
    k_scan1<<<NB_SCAN, 1024, 0, s_csr>>>();
    k_scan2<<<1, 128, 0, s_csr>>>();
    k_scan3<<<NB_SCAN, 1024, 0, s_csr>>>();
    k_scatter<<<(N_EDGES + 255) / 256, 256, 0, s_csr>>>(ei, ew);
    cudaEventRecord(e_join, s_csr);

    // --- branch A (weights + GEMM1) on default stream ---
    k_prepW<<<(N_FEAT * HIDDEN + 255) / 256, 256>>>(W1);
    k_gemm1_mma<<<(N_NODES + 127) / 128, 256>>>(x);

    // join: prop1 needs both branches
    cudaStreamWaitEvent(0, e_join, 0);
    k_prop1<<<N_NODES, 128>>>(b1);
    k_gemm2<<<(N_NODES + 127) / 128, 256>>>(W2);
    k_prop2<<<N_NODES, 64>>>(b2, out);
}

// round 15
// speedup vs baseline: 1.1951x; 1.0504x over previous
#include <cuda_runtime.h>
#include <cuda_bf16.h>
#include <cstdint>

#define N_NODES   100000
#define N_EDGES   1600000
#define N_FEAT    512
#define HIDDEN    128
#define N_CLASSES 64

#define NB_SCAN   ((N_NODES + 1023) / 1024)   // 98

// ---------------- scratch (static device globals; no allocation) -------------
__device__ float g_h1[N_NODES * HIDDEN];      // x @ W1
__device__ float g_h [N_NODES * HIDDEN];      // relu(prop1 + b1)
__device__ float g_h2[N_NODES * N_CLASSES];   // h @ W2
__device__ int   g_counts[N_NODES];
__device__ int   g_cursor[N_NODES];
__device__ int   g_rowptr[N_NODES + 1];
__device__ int   g_bsums[128];
__device__ int   g_esrc[N_EDGES];             // CSR-by-dst: src per slot
__device__ float g_ewt [N_EDGES];             // CSR-by-dst: weight per slot
__device__ int   g_is64;                      // 1 if edge_index is int64
// W1^T split into bf16 hi/lo:  Wt[n][k] = W1[k][n]
__device__ __align__(16) __nv_bfloat16 g_Wt_hi[HIDDEN * N_FEAT];
__device__ __align__(16) __nv_bfloat16 g_Wt_lo[HIDDEN * N_FEAT];
// W2^T split into bf16 hi/lo:  W2t[n][k] = W2[k][n]
__device__ __align__(16) __nv_bfloat16 g_W2t_hi[N_CLASSES * HIDDEN];
__device__ __align__(16) __nv_bfloat16 g_W2t_lo[N_CLASSES * HIDDEN];

// ================= helpers ====================================================
__device__ __forceinline__ uint32_t smem_u32(const void* p) {
    uint32_t a;
    asm("{ .reg .u64 t; cvta.to.shared.u64 t, %1; cvt.u32.u64 %0, t; }"
        : "=r"(a) : "l"(p));
    return a;
}
__device__ __forceinline__ void ldsm_x4(uint32_t* r, uint32_t addr) {
    asm volatile("ldmatrix.sync.aligned.m8n8.x4.shared.b16 {%0,%1,%2,%3}, [%4];"
        : "=r"(r[0]), "=r"(r[1]), "=r"(r[2]), "=r"(r[3]) : "r"(addr));
}
__device__ __forceinline__ void mma16816(float* c, const uint32_t* a,
                                         const uint32_t* b) {
    asm volatile(
        "mma.sync.aligned.m16n8k16.row.col.f32.bf16.bf16.f32 "
        "{%0,%1,%2,%3}, {%4,%5,%6,%7}, {%8,%9}, {%0,%1,%2,%3};"
        : "+f"(c[0]), "+f"(c[1]), "+f"(c[2]), "+f"(c[3])
        : "r"(a[0]), "r"(a[1]), "r"(a[2]), "r"(a[3]), "r"(b[0]), "r"(b[1]));
}
__device__ __forceinline__ uint32_t pack_bf2(__nv_bfloat16 a, __nv_bfloat16 b) {
    __nv_bfloat162 t = __halves2bfloat162(a, b);
    uint32_t u;
    *(__nv_bfloat162*)&u = t;
    return u;
}
// split float4 -> hi/lo packed pairs
__device__ __forceinline__ void split4(float4 v, uint2* ph, uint2* pl) {
    __nv_bfloat16 h0 = __float2bfloat16(v.x);
    __nv_bfloat16 h1 = __float2bfloat16(v.y);
    __nv_bfloat16 h2 = __float2bfloat16(v.z);
    __nv_bfloat16 h3 = __float2bfloat16(v.w);
    __nv_bfloat16 l0 = __float2bfloat16(v.x - __bfloat162float(h0));
    __nv_bfloat16 l1 = __float2bfloat16(v.y - __bfloat162float(h1));
    __nv_bfloat16 l2 = __float2bfloat16(v.z - __bfloat162float(h2));
    __nv_bfloat16 l3 = __float2bfloat16(v.w - __bfloat162float(h3));
    *ph = make_uint2(pack_bf2(h0, h1), pack_bf2(h2, h3));
    *pl = make_uint2(pack_bf2(l0, l1), pack_bf2(l2, l3));
}

// ---------------- dtype probe -------------------------------------------------
__global__ void k_probe(const void* __restrict__ ei_raw) {
    const long long* p = (const long long*)ei_raw;
    int ok = 1;
    #pragma unroll
    for (int i = 0; i < 8; i++) {
        long long v = p[(size_t)i * 199999];
        if (v < 0 || v >= N_NODES) ok = 0;
    }
    g_is64 = ok;
}

__device__ __forceinline__ int load_idx(const void* ei_raw, size_t pos, int is64) {
    if (is64) return (int)((const long long*)ei_raw)[pos];
    return ((const int*)ei_raw)[pos];
}

// ---------------- CSR build ---------------------------------------------------
__global__ void k_zero_counts() {
    int i = blockIdx.x * blockDim.x + threadIdx.x;
    if (i < N_NODES) { g_counts[i] = 0; g_cursor[i] = 0; }
}

__global__ void k_hist(const void* __restrict__ ei_raw) {
    int e = blockIdx.x * blockDim.x + threadIdx.x;
    if (e < N_EDGES) {
        int dst = load_idx(ei_raw, (size_t)N_EDGES + e, g_is64);
        if ((unsigned)dst < N_NODES)
            atomicAdd(&g_counts[dst], 1);
    }
}

__global__ void k_scan1() {
    __shared__ int sh[1024];
    int tid = threadIdx.x;
    int gid = blockIdx.x * 1024 + tid;
    int v = (gid < N_NODES) ? g_counts[gid] : 0;
    sh[tid] = v;
    __syncthreads();
    #pragma unroll
    for (int off = 1; off < 1024; off <<= 1) {
        int t = (tid >= off) ? sh[tid - off] : 0;
        __syncthreads();
        sh[tid] += t;
        __syncthreads();
    }
    if (gid < N_NODES) g_rowptr[gid] = sh[tid] - v;
    if (tid == 1023) g_bsums[blockIdx.x] = sh[1023];
}

__global__ void k_scan2() {
    __shared__ int sh[128];
    int tid = threadIdx.x;
    int v = (tid < NB_SCAN) ? g_bsums[tid] : 0;
    sh[tid] = v;
    __syncthreads();
    #pragma unroll
    for (int off = 1; off < 128; off <<= 1) {
        int t = (tid >= off) ? sh[tid - off] : 0;
        __syncthreads();
        sh[tid] += t;
        __syncthreads();
    }
    if (tid < NB_SCAN) g_bsums[tid] = sh[tid] - v;
}

__global__ void k_scan3() {
    int gid = blockIdx.x * 1024 + threadIdx.x;
    if (gid < N_NODES) g_rowptr[gid] += g_bsums[blockIdx.x];
    if (gid == 0) g_rowptr[N_NODES] = N_EDGES;
}

__global__ void k_scatter(const void* __restrict__ ei_raw,
                          const float* __restrict__ ew) {
    int e = blockIdx.x * blockDim.x + threadIdx.x;
    if (e < N_EDGES) {
        int is64 = g_is64;
        int src = load_idx(ei_raw, (size_t)e, is64);
        int dst = load_idx(ei_raw, (size_t)N_EDGES + e, is64);
        if ((unsigned)dst >= N_NODES || (unsigned)src >= N_NODES) return;
        int pos = g_rowptr[dst] + atomicAdd(&g_cursor[dst], 1);
        g_esrc[pos] = src;
        g_ewt[pos]  = ew[e];
    }
}

// ---------------- weight prep: transpose + bf16 hi/lo split ------------------
__global__ void k_prepW(const float* __restrict__ W) {
    int i = blockIdx.x * blockDim.x + threadIdx.x;   // i over 512*128
    if (i < N_FEAT * HIDDEN) {
        int k = i / HIDDEN;
        int n = i % HIDDEN;
        float v = W[i];
        __nv_bfloat16 hi = __float2bfloat16(v);
        __nv_bfloat16 lo = __float2bfloat16(v - __bfloat162float(hi));
        g_Wt_hi[(size_t)n * N_FEAT + k] = hi;
        g_Wt_lo[(size_t)n * N_FEAT + k] = lo;
    }
}

__global__ void k_prepW2(const float* __restrict__ W) {
    int i = blockIdx.x * blockDim.x + threadIdx.x;   // i over 128*64
    if (i < HIDDEN * N_CLASSES) {
        int k = i / N_CLASSES;
        int n = i % N_CLASSES;
        float v = W[i];
        __nv_bfloat16 hi = __float2bfloat16(v);
        __nv_bfloat16 lo = __float2bfloat16(v - __bfloat162float(hi));
        g_W2t_hi[(size_t)n * HIDDEN + k] = hi;
        g_W2t_lo[(size_t)n * HIDDEN + k] = lo;
    }
}

// ---------------- GEMM1 (mma.sync bf16, 2-term split): h1 = x @ W1 -----------
// CTA tile 128x128, K chunks of 32, 8 warps (4x2), warp tile 32x64.
// D[m][n] = sum_k A[m][k] * B[n][k];  C = Ah*Bh + Ah*Bl + Al*Bh.
#define APAD 40   // 32 + 8 pad, rows are 80B -> ldmatrix conflict-free

__global__ __launch_bounds__(256, 2)
void k_gemm1_mma(const float* __restrict__ X) {
    __shared__ __align__(16) __nv_bfloat16 sAh[128][APAD];
    __shared__ __align__(16) __nv_bfloat16 sAl[128][APAD];
    __shared__ __align__(16) __nv_bfloat16 sBh[128][APAD];
    __shared__ __align__(16) __nv_bfloat16 sBl[128][APAD];

    const int tid = threadIdx.x;
    const int wid = tid >> 5;
    const int lane = tid & 31;
    const int warp_m = wid >> 1;          // 0..3
    const int warp_n = wid & 1;           // 0..1
    const int m0 = blockIdx.x * 128;

    // staging mapping: each thread owns 1 row-half (16 elems)
    const int ar = tid >> 1;              // 0..127
    const int ac = (tid & 1) * 16;        // 0 or 16
    const bool aval = (m0 + ar) < N_NODES;
    const float* xrow = X + (size_t)(m0 + ar) * N_FEAT + ac;
    const __nv_bfloat16* bhrow = g_Wt_hi + (size_t)ar * N_FEAT + ac;
    const __nv_bfloat16* blrow = g_Wt_lo + (size_t)ar * N_FEAT + ac;

    // ldmatrix addresses
    const uint32_t uAh = smem_u32(&sAh[0][0]);
    const uint32_t uAl = smem_u32(&sAl[0][0]);
    const uint32_t uBh = smem_u32(&sBh[0][0]);
    const uint32_t uBl = smem_u32(&sBl[0][0]);
    const int a_row = warp_m * 32 + (lane & 7) + ((lane >> 3) & 1) * 8;
    const int a_col = ((lane >> 4) & 1) * 8;
    uint32_t adAh[2], adAl[2];
    #pragma unroll
    for (int mt = 0; mt < 2; mt++) {
        uint32_t off = (uint32_t)((a_row + mt * 16) * APAD + a_col) * 2;
        adAh[mt] = uAh + off;
        adAl[mt] = uAl + off;
    }
    const int b_row = warp_n * 64 + (lane & 7) + ((lane >> 4) & 1) * 8;
    const int b_col = ((lane >> 3) & 1) * 8;
    uint32_t adBh[4], adBl[4];
    #pragma unroll
    for (int p = 0; p < 4; p++) {
        uint32_t off = (uint32_t)((b_row + p * 16) * APAD + b_col) * 2;
        adBh[p] = uBh + off;
        adBl[p] = uBl + off;
    }

    float acc[2][8][4];
    #pragma unroll
    for (int mt = 0; mt < 2; mt++)
        #pragma unroll
        for (int nt = 0; nt < 8; nt++)
            #pragma unroll
            for (int q = 0; q < 4; q++) acc[mt][nt][q] = 0.f;

    // prefetch A chunk 0
    float4 av[4];
    #pragma unroll
    for (int i = 0; i < 4; i++)
        av[i] = aval ? *(const float4*)(xrow + i * 4)
                     : make_float4(0.f, 0.f, 0.f, 0.f);

    for (int kc = 0; kc < N_FEAT / 32; kc++) {
        __syncthreads();     // previous chunk consumed
        // --- STS A (split to hi/lo) ---
        #pragma unroll
        for (int i = 0; i < 4; i++) {
            float4 v = av[i];
            __nv_bfloat16 h0 = __float2bfloat16(v.x);
            __nv_bfloat16 h1 = __float2bfloat16(v.y);
            __nv_bfloat16 h2 = __float2bfloat16(v.z);
            __nv_bfloat16 h3 = __float2bfloat16(v.w);
            __nv_bfloat16 l0 = __float2bfloat16(v.x - __bfloat162float(h0));
            __nv_bfloat16 l1 = __float2bfloat16(v.y - __bfloat162float(h1));
            __nv_bfloat16 l2 = __float2bfloat16(v.z - __bfloat162float(h2));
            __nv_bfloat16 l3 = __float2bfloat16(v.w - __bfloat162float(h3));
            *(uint2*)&sAh[ar][ac + i * 4] =
                make_uint2(pack_bf2(h0, h1), pack_bf2(h2, h3));
            *(uint2*)&sAl[ar][ac + i * 4] =
                make_uint2(pack_bf2(l0, l1), pack_bf2(l2, l3));
        }
        // --- LDG+STS B (prepped bf16, L2-resident) ---
        #pragma unroll
        for (int j = 0; j < 2; j++) {
            *(uint4*)&sBh[ar][ac + j * 8] =
                *(const uint4*)(bhrow + kc * 32 + j * 8);
            *(uint4*)&sBl[ar][ac + j * 8] =
                *(const uint4*)(blrow + kc * 32 + j * 8);
        }
        __syncthreads();

        // prefetch next A chunk (overlaps with mma below)
        if (kc + 1 < N_FEAT / 32) {
            #pragma unroll
            for (int i = 0; i < 4; i++)
                av[i] = aval ? *(const float4*)(xrow + (kc + 1) * 32 + i * 4)
                             : make_float4(0.f, 0.f, 0.f, 0.f);
        }

        // --- MMA over the 2 k-steps of this chunk ---
        #pragma unroll
        for (int ks = 0; ks < 2; ks++) {
            uint32_t Ah0[4], Ah1[4], Al0[4], Al1[4];
            ldsm_x4(Ah0, adAh[0] + ks * 32);
            ldsm_x4(Ah1, adAh[1] + ks * 32);
            ldsm_x4(Al0, adAl[0] + ks * 32);
            ldsm_x4(Al1, adAl[1] + ks * 32);
            #pragma unroll
            for (int p = 0; p < 4; p++) {
                uint32_t Bh[4], Bl[4];
                ldsm_x4(Bh, adBh[p] + ks * 32);
                ldsm_x4(Bl, adBl[p] + ks * 32);
                // Ah*Bh
                mma16816(acc[0][2 * p + 0], Ah0, Bh + 0);
                mma16816(acc[0][2 * p + 1], Ah0, Bh + 2);
                mma16816(acc[1][2 * p + 0], Ah1, Bh + 0);
                mma16816(acc[1][2 * p + 1], Ah1, Bh + 2);
                // Al*Bh
                mma16816(acc[0][2 * p + 0], Al0, Bh + 0);
                mma16816(acc[0][2 * p + 1], Al0, Bh + 2);
                mma16816(acc[1][2 * p + 0], Al1, Bh + 0);
                mma16816(acc[1][2 * p + 1], Al1, Bh + 2);
                // Ah*Bl
                mma16816(acc[0][2 * p + 0], Ah0, Bl + 0);
                mma16816(acc[0][2 * p + 1], Ah0, Bl + 2);
                mma16816(acc[1][2 * p + 0], Ah1, Bl + 0);
                mma16816(acc[1][2 * p + 1], Ah1, Bl + 2);
            }
        }
    }

    // --- epilogue: acc -> g_h1 ---
    #pragma unroll
    for (int mt = 0; mt < 2; mt++) {
        int row = m0 + warp_m * 32 + mt * 16 + (lane >> 2);
        #pragma unroll
        for (int nt = 0; nt < 8; nt++) {
            int col = warp_n * 64 + nt * 8 + (lane & 3) * 2;
            if (row < N_NODES)
                *(float2*)&g_h1[(size_t)row * HIDDEN + col] =
                    make_float2(acc[mt][nt][0], acc[mt][nt][1]);
            if (row + 8 < N_NODES)
                *(float2*)&g_h1[(size_t)(row + 8) * HIDDEN + col] =
                    make_float2(acc[mt][nt][2], acc[mt][nt][3]);
        }
    }
}

// ---------------- prop1: h = relu(segment_sum(w*h1[src]) + b1) ---------------
__global__ __launch_bounds__(128)
void k_prop1(const float* __restrict__ b1) {
    __shared__ int   ss[128];
    __shared__ float sw[128];
    const int n = blockIdx.x;
    const int f = threadIdx.x;
    float a0 = b1[f], a1 = 0.f, a2 = 0.f, a3 = 0.f;
    const int beg = g_rowptr[n];
    const int end = g_rowptr[n + 1];
    for (int base = beg; base < end; base += 128) {
        int cnt = min(128, end - base);
        if (f < cnt) { ss[f] = g_esrc[base + f]; sw[f] = g_ewt[base + f]; }
        __syncthreads();
        int i = 0;
        for (; i + 4 <= cnt; i += 4) {
            float v0 = g_h1[(size_t)ss[i + 0] * HIDDEN + f];
            float v1 = g_h1[(size_t)ss[i + 1] * HIDDEN + f];
            float v2 = g_h1[(size_t)ss[i + 2] * HIDDEN + f];
            float v3 = g_h1[(size_t)ss[i + 3] * HIDDEN + f];
            a0 = fmaf(sw[i + 0], v0, a0);
            a1 = fmaf(sw[i + 1], v1, a1);
            a2 = fmaf(sw[i + 2], v2, a2);
            a3 = fmaf(sw[i + 3], v3, a3);
        }
        for (; i < cnt; i++)
            a0 = fmaf(sw[i], g_h1[(size_t)ss[i] * HIDDEN + f], a0);
        __syncthreads();
    }
    float acc = (a0 + a1) + (a2 + a3);
    g_h[(size_t)n * HIDDEN + f] = fmaxf(acc, 0.f);
}

// ---------------- GEMM2 (lean mma.sync bf16 split): h2 = h @ W2 --------------
// CTA tile 128x64, K=128 in 4 chunks of 32. 8 warps (4x2), warp tile 32x32.
// Static smem: A 2x(128x40), B 2x(64x40) bf16 = 30 KB.
__global__ __launch_bounds__(256, 2)
void k_gemm2_mma() {
    __shared__ __align__(16) __nv_bfloat16 sAh[128][APAD];
    __shared__ __align__(16) __nv_bfloat16 sAl[128][APAD];
    __shared__ __align__(16) __nv_bfloat16 sBh[64][APAD];
    __shared__ __align__(16) __nv_bfloat16 sBl[64][APAD];

    const int tid = threadIdx.x;
    const int wid = tid >> 5;
    const int lane = tid & 31;
    const int warp_m = wid >> 1;          // 0..3
    const int warp_n = wid & 1;           // 0..1
    const int m0 = blockIdx.x * 128;

    // A staging: thread owns 16 elems of one row-chunk
    const int ar = tid >> 1;
    const int ac = (tid & 1) * 16;
    const bool aval = (m0 + ar) < N_NODES;
    const float* hrow = g_h + (size_t)(m0 + ar) * HIDDEN + ac;
    // B staging: 64 rows x 32 cols per chunk; thread owns 8 elems
    const int br = tid >> 2;              // 0..63
    const int bc = (tid & 3) * 8;         // 0,8,16,24
    const __nv_bfloat16* bhrow = g_W2t_hi + (size_t)br * HIDDEN + bc;
    const __nv_bfloat16* blrow = g_W2t_lo + (size_t)br * HIDDEN + bc;

    const uint32_t uAh = smem_u32(&sAh[0][0]);
    const uint32_t uAl = smem_u32(&sAl[0][0]);
    const uint32_t uBh = smem_u32(&sBh[0][0]);
    const uint32_t uBl = smem_u32(&sBl[0][0]);
    const int a_row = warp_m * 32 + (lane & 7) + ((lane >> 3) & 1) * 8;
    const int a_col = ((lane >> 4) & 1) * 8;
    uint32_t adAh[2], adAl[2];
    #pragma unroll
    for (int mt = 0; mt < 2; mt++) {
        uint32_t off = (uint32_t)((a_row + mt * 16) * APAD + a_col) * 2;
        adAh[mt] = uAh + off;
        adAl[mt] = uAl + off;
    }
    const int b_row = warp_n * 32 + (lane & 7) + ((lane >> 4) & 1) * 8;
    const int b_col = ((lane >> 3) & 1) * 8;
    uint32_t adBh[2], adBl[2];
    #pragma unroll
    for (int p = 0; p < 2; p++) {
        uint32_t off = (uint32_t)((b_row + p * 16) * APAD + b_col) * 2;
        adBh[p] = uBh + off;
        adBl[p] = uBl + off;
    }

    float acc[2][4][4];
    #pragma unroll
    for (int mt = 0; mt < 2; mt++)
        #pragma unroll
        for (int nt = 0; nt < 4; nt++)
            #pragma unroll
            for (int q = 0; q < 4; q++) acc[mt][nt][q] = 0.f;

    // prefetch A chunk 0
    float4 av[4];
    #pragma unroll
    for (int i = 0; i < 4; i++)
        av[i] = aval ? *(const float4*)(hrow + i * 4)
                     : make_float4(0.f, 0.f, 0.f, 0.f);

    #pragma unroll
    for (int kc = 0; kc < HIDDEN / 32; kc++) {
        __syncthreads();
        #pragma unroll
        for (int i = 0; i < 4; i++) {
            uint2 ph, pl;
            split4(av[i], &ph, &pl);
            *(uint2*)&sAh[ar][ac + i * 4] = ph;
            *(uint2*)&sAl[ar][ac + i * 4] = pl;
        }
        *(uint4*)&sBh[br][bc] = *(const uint4*)(bhrow + kc * 32);
        *(uint4*)&sBl[br][bc] = *(const uint4*)(blrow + kc * 32);
        __syncthreads();

        if (kc + 1 < HIDDEN / 32) {
            #pragma unroll
            for (int i = 0; i < 4; i++)
                av[i] = aval ? *(const float4*)(hrow + (kc + 1) * 32 + i * 4)
                             : make_float4(0.f, 0.f, 0.f, 0.f);
        }

        #pragma unroll
        for (int ks = 0; ks < 2; ks++) {
            uint32_t Ah0[4], Ah1[4], Al0[4], Al1[4];
            ldsm_x4(Ah0, adAh[0] + ks * 32);
            ldsm_x4(Ah1, adAh[1] + ks * 32);
            ldsm_x4(Al0, adAl[0] + ks * 32);
            ldsm_x4(Al1, adAl[1] + ks * 32);
            #pragma unroll
            for (int p = 0; p < 2; p++) {
                uint32_t Bh[4], Bl[4];
                ldsm_x4(Bh, adBh[p] + ks * 32);
                ldsm_x4(Bl, adBl[p] + ks * 32);
                mma16816(acc[0][2 * p + 0], Ah0, Bh + 0);
                mma16816(acc[0][2 * p + 1], Ah0, Bh + 2);
                mma16816(acc[1][2 * p + 0], Ah1, Bh + 0);
                mma16816(acc[1][2 * p + 1], Ah1, Bh + 2);
                mma16816(acc[0][2 * p + 0], Al0, Bh + 0);
                mma16816(acc[0][2 * p + 1], Al0, Bh + 2);
                mma16816(acc[1][2 * p + 0], Al1, Bh + 0);
                mma16816(acc[1][2 * p + 1], Al1, Bh + 2);
                mma16816(acc[0][2 * p + 0], Ah0, Bl + 0);
                mma16816(acc[0][2 * p + 1], Ah0, Bl + 2);
                mma16816(acc[1][2 * p + 0], Ah1, Bl + 0);
                mma16816(acc[1][2 * p + 1], Ah1, Bl + 2);
            }
        }
    }

    #pragma unroll
    for (int mt = 0; mt < 2; mt++) {
        int row = m0 + warp_m * 32 + mt * 16 + (lane >> 2);
        #pragma unroll
        for (int nt = 0; nt < 4; nt++) {
            int col = warp_n * 32 + nt * 8 + (lane & 3) * 2;
            if (row < N_NODES)
                *(float2*)&g_h2[(size_t)row * N_CLASSES + col] =
                    make_float2(acc[mt][nt][0], acc[mt][nt][1]);
            if (row + 8 < N_NODES)
                *(float2*)&g_h2[(size_t)(row + 8) * N_CLASSES + col] =
                    make_float2(acc[mt][nt][2], acc[mt][nt][3]);
        }
    }
}

// ---------------- prop2: out = segment_sum(w*h2[src]) + b2 -------------------
__global__ __launch_bounds__(64)
void k_prop2(const float* __restrict__ b2, float* __restrict__ out) {
    __shared__ int   ss[64];
    __shared__ float sw[64];
    const int n = blockIdx.x;
    const int f = threadIdx.x;
    float a0 = b2[f], a1 = 0.f, a2 = 0.f, a3 = 0.f;
    const int beg = g_rowptr[n];
    const int end = g_rowptr[n + 1];
    for (int base = beg; base < end; base += 64) {
        int cnt = min(64, end - base);
        if (f < cnt) { ss[f] = g_esrc[base + f]; sw[f] = g_ewt[base + f]; }
        __syncthreads();
        int i = 0;
        for (; i + 4 <= cnt; i += 4) {
            float v0 = g_h2[(size_t)ss[i + 0] * N_CLASSES + f];
            float v1 = g_h2[(size_t)ss[i + 1] * N_CLASSES + f];
            float v2 = g_h2[(size_t)ss[i + 2] * N_CLASSES + f];
            float v3 = g_h2[(size_t)ss[i + 3] * N_CLASSES + f];
            a0 = fmaf(sw[i + 0], v0, a0);
            a1 = fmaf(sw[i + 1], v1, a1);
            a2 = fmaf(sw[i + 2], v2, a2);
            a3 = fmaf(sw[i + 3], v3, a3);
        }
        for (; i < cnt; i++)
            a0 = fmaf(sw[i], g_h2[(size_t)ss[i] * N_CLASSES + f], a0);
        __syncthreads();
    }
    out[(size_t)n * N_CLASSES + f] = (a0 + a1) + (a2 + a3);
}

// ---------------- launch ------------------------------------------------------
extern "C" void kernel_launch(void* const* d_in, const int* in_sizes, int n_in,
                              void* d_out, int out_size) {
    const float* x  = (const float*)d_in[0];
    const void*  ei = d_in[1];
    const float* ew = (const float*)d_in[2];
    const float* W1 = (const float*)d_in[3];
    const float* b1 = (const float*)d_in[4];
    const float* W2 = (const float*)d_in[5];
    const float* b2 = (const float*)d_in[6];
    float* out = (float*)d_out;

    // lazy host-side stream/event objects (no device memory involved)
    static cudaStream_t s_csr = nullptr;
    static cudaEvent_t  e_fork = nullptr, e_join = nullptr;
    if (s_csr == nullptr) {
        cudaStreamCreateWithFlags(&s_csr, cudaStreamNonBlocking);
        cudaEventCreateWithFlags(&e_fork, cudaEventDisableTiming);
        cudaEventCreateWithFlags(&e_join, cudaEventDisableTiming);
    }

    // fork: CSR chain + W2 prep on s_csr, GEMM1 chain on the capture stream
    cudaEventRecord(e_fork, 0);
    cudaStreamWaitEvent(s_csr, e_fork, 0);

    // --- branch B (CSR build + W2 prep) on s_csr ---
    k_probe<<<1, 1, 0, s_csr>>>(ei);
    k_zero_counts<<<(N_NODES + 255) / 256, 256, 0, s_csr>>>();
    k_hist<<<(N_EDGES + 255) / 256, 256, 0, s_csr>>>(ei);
    k_scan1<<<NB_SCAN, 1024, 0, s_csr>>>();
    k_scan2<<<1, 128, 0, s_csr>>>();
    k_scan3<<<NB_SCAN, 1024, 0, s_csr>>>();
    k_scatter<<<(N_EDGES + 255) / 256, 256, 0, s_csr>>>(ei, ew);
    k_prepW2<<<(HIDDEN * N_CLASSES + 255) / 256, 256, 0, s_csr>>>(W2);
    cudaEventRecord(e_join, s_csr);

    // --- branch A (W1 prep + GEMM1) on default stream ---
    k_prepW<<<(N_FEAT * HIDDEN + 255) / 256, 256>>>(W1);
    k_gemm1_mma<<<(N_NODES + 127) / 128, 256>>>(x);

    // join: prop1 needs both branches
    cudaStreamWaitEvent(0, e_join, 0);
    k_prop1<<<N_NODES, 128>>>(b1);
    k_gemm2_mma<<<(N_NODES + 127) / 128, 256>>>();
    k_prop2<<<N_NODES, 64>>>(b2, out);
}